// round 5
// baseline (speedup 1.0000x reference)
#include <cuda_runtime.h>
#include <cuda_bf16.h>
#include <math.h>
#include <stdint.h>

#define N 8192
#define D 128
#define NC 512
#define MAXM 64

// ---------------- scratch (device globals; no allocation allowed) ----------
__device__ __align__(16) float g_enorm[N * D];
__device__ __align__(16) __nv_bfloat16 g_hi[N * D];
__device__ __align__(16) __nv_bfloat16 g_mid[N * D];
__device__ int   g_cnt[NC];          // zero at module load; re-zeroed by k_final
__device__ int   g_members[NC * MAXM];
__device__ float g_lsep[N];
__device__ float g_samesum[N];
__device__ float g_sall[N];
__device__ int   g_is64;

__device__ __forceinline__ float an_exp(float s) {
    float t = fmaxf(s + 0.4f, 0.0f);
    return __expf(80.0f * t * (s - 0.4f));
}

__device__ __forceinline__ int get_label(const void* lab, int i) {
    if (g_is64) return (int)((const long long*)lab)[i];
    return ((const int*)lab)[i];
}

__device__ __forceinline__ uint32_t smem_u32(const void* p) {
    uint32_t a;
    asm("{ .reg .u64 t; cvta.to.shared.u64 t, %1; cvt.u32.u64 %0, t; }" : "=r"(a) : "l"(p));
    return a;
}
__device__ __forceinline__ void cpa16(uint32_t dst, const void* src) {
    asm volatile("cp.async.cg.shared.global [%0], [%1], 16;" :: "r"(dst), "l"(src) : "memory");
}
__device__ __forceinline__ void ldsm4(uint32_t* r, uint32_t addr) {
    asm volatile("ldmatrix.sync.aligned.m8n8.x4.shared.b16 {%0,%1,%2,%3}, [%4];"
        : "=r"(r[0]), "=r"(r[1]), "=r"(r[2]), "=r"(r[3]) : "r"(addr));
}
__device__ __forceinline__ void mma_bf16(float* d, const uint32_t* a, uint32_t b0, uint32_t b1) {
    asm volatile(
        "mma.sync.aligned.m16n8k16.row.col.f32.bf16.bf16.f32 "
        "{%0,%1,%2,%3}, {%4,%5,%6,%7}, {%8,%9}, {%0,%1,%2,%3};\n"
        : "+f"(d[0]), "+f"(d[1]), "+f"(d[2]), "+f"(d[3])
        : "r"(a[0]), "r"(a[1]), "r"(a[2]), "r"(a[3]), "r"(b0), "r"(b1));
}

// ---------------- kernel 1: normalize + bf16 split + lists + zero sall -----
// (g_cnt arrives zeroed: module-load init for run 1, k_final re-zeroes after)
__global__ void k_norm(const float* __restrict__ in, const void* __restrict__ lab) {
    int gid = blockIdx.x * blockDim.x + threadIdx.x;
    if (gid < N) g_sall[gid] = 0.0f;
    if (gid == 0) {
        const int* w = (const int*)lab;
        int bad = 0;
        #pragma unroll
        for (int k = 1; k < 128; k += 2) bad |= w[k];
        g_is64 = (bad == 0);
    }
    int row  = blockIdx.x * 8 + (threadIdx.x >> 5);
    int lane = threadIdx.x & 31;
    float4 v = *(const float4*)(in + row * D + lane * 4);
    float ss = v.x * v.x + v.y * v.y + v.z * v.z + v.w * v.w;
    #pragma unroll
    for (int m = 16; m >= 1; m >>= 1) ss += __shfl_xor_sync(0xffffffffu, ss, m);
    float inv = 1.0f / fmaxf(sqrtf(ss), 1e-12f);
    float o[4] = {v.x * inv, v.y * inv, v.z * inv, v.w * inv};
    float4 of; of.x = o[0]; of.y = o[1]; of.z = o[2]; of.w = o[3];
    *(float4*)(g_enorm + row * D + lane * 4) = of;
    #pragma unroll
    for (int c = 0; c < 4; c++) {
        __nv_bfloat16 h = __float2bfloat16(o[c]);
        float r = o[c] - __bfloat162float(h);
        g_hi [row * D + lane * 4 + c] = h;
        g_mid[row * D + lane * 4 + c] = __float2bfloat16(r);
    }
    if (lane == 0) {
        int c = get_label(lab, row);
        int p = atomicAdd(&g_cnt[c], 1);
        if (p < MAXM) g_members[c * MAXM + p] = row;
    }
}

// ---------------- kernel 2: per-class positives, warp-per-anchor -----------
__global__ void k_class() {
    int c = blockIdx.x;
    __shared__ int   mlist[MAXM];
    __shared__ float se[MAXM * 129];
    int m = g_cnt[c];
    if (m > MAXM) m = MAXM;
    if (m == 0) return;
    int tid = threadIdx.x, lane = tid & 31, wid = tid >> 5;
    if (tid < m) mlist[tid] = g_members[c * MAXM + tid];
    __syncthreads();
    for (int p = tid; p < m * D; p += blockDim.x) {
        int r = p >> 7, k = p & 127;
        se[r * 129 + k] = g_enorm[mlist[r] * D + k];
    }
    __syncthreads();
    for (int a = wid; a < m; a += 4) {
        int b0 = lane, b1 = lane + 32;
        float s0 = 0.0f, s1 = 0.0f;
        const float* ra = se + a * 129;
        #pragma unroll 8
        for (int k = 0; k < D; k++) {
            float av = ra[k];
            s0 = fmaf(av, se[b0 * 129 + k], s0);
            s1 = fmaf(av, se[b1 * 129 + k], s1);
        }
        float ap0 = -1e30f, ap1 = -1e30f, an0 = 0.0f, an1 = 0.0f;
        bool v0 = (b0 < m && b0 != a), v1 = (b1 < m && b1 != a);
        if (v0) { ap0 = -80.0f * fmaxf(1.4f - s0, 0.0f) * (s0 - 0.6f); an0 = an_exp(s0); }
        if (v1) { ap1 = -80.0f * fmaxf(1.4f - s1, 0.0f) * (s1 - 0.6f); an1 = an_exp(s1); }
        float mx = fmaxf(ap0, ap1);
        #pragma unroll
        for (int k = 16; k >= 1; k >>= 1) mx = fmaxf(mx, __shfl_xor_sync(0xffffffffu, mx, k));
        float es = (v0 ? __expf(ap0 - mx) : 0.0f) + (v1 ? __expf(ap1 - mx) : 0.0f);
        float sa = an0 + an1;
        #pragma unroll
        for (int k = 16; k >= 1; k >>= 1) {
            es += __shfl_xor_sync(0xffffffffu, es, k);
            sa += __shfl_xor_sync(0xffffffffu, sa, k);
        }
        if (lane == 0) {
            g_lsep[mlist[a]]    = mx + logf(es);
            g_samesum[mlist[a]] = sa;
        }
    }
}

// ---------------- kernel 3: pipelined mma.sync GEMM + fused an-sumexp ------
// BK=32: per-stage arrays of 128 rows x 32 halves (64B), row stride 80B.
// ldmatrix conflict-free: banks (20*g) mod 32 distinct for g=0..7.
#define SROW   80
#define ARR    (128 * SROW)          // 10240 B per array
#define STG    (4 * ARR)             // 40960 B per stage
#define SMEM_SZ (2 * STG)            // 81920 B

__global__ void __launch_bounds__(256, 2) k_main_m() {
    int b = blockIdx.x;
    int r = (int)((__fsqrt_rn(8.0f * (float)b + 1.0f) - 1.0f) * 0.5f);
    while ((r + 1) * (r + 2) / 2 <= b) r++;
    while (r * (r + 1) / 2 > b) r--;
    int bi = b - r * (r + 1) / 2;
    int bj = r;

    extern __shared__ char sm[];
    uint32_t sb = smem_u32(sm);
    int tid = threadIdx.x;
    int lane = tid & 31, wid = tid >> 5;
    int g = lane >> 2, t = lane & 3;
    int wm = wid & 3, wn = wid >> 2;       // 4x2 warp grid, warp tile 32x64
    int rowBase = bi * 128, colBase = bj * 128;

    // per-thread load slots: 2048 uint4 per stage / 256 threads = 8
    // slot s (0..7): array = s>>1, idx = (s&1)*256 + tid; row = idx>>2, k4 = idx&3
    uint32_t ld_so[8];
    size_t   ld_gi[8];
    #pragma unroll
    for (int s = 0; s < 8; s++) {
        int arr = s >> 1;
        int idx = (s & 1) * 256 + tid;
        int row = idx >> 2, k4 = idx & 3;
        ld_so[s] = (uint32_t)(arr * ARR + row * SROW + k4 * 16);
        int base = (arr & 1) ? colBase : rowBase;     // arrays: 0=A_HI? see below
        ld_gi[s] = (size_t)(base + row) * 16 + k4;
    }
    // array order: 0=A_HI, 1=B_HI, 2=A_MID, 3=B_MID  (arr&1 -> B)
    const uint4* gsrc[4] = { (const uint4*)g_hi,  (const uint4*)g_hi,
                             (const uint4*)g_mid, (const uint4*)g_mid };

    uint32_t lmo = (uint32_t)((lane & 15) * SROW + (lane >> 4) * 16);
    uint32_t aHi  = sb + 0 * ARR + (uint32_t)(wm * 32) * SROW + lmo;
    uint32_t bHi  = sb + 1 * ARR + (uint32_t)(wn * 64) * SROW + lmo;
    uint32_t aMid = sb + 2 * ARR + (uint32_t)(wm * 32) * SROW + lmo;
    uint32_t bMid = sb + 3 * ARR + (uint32_t)(wn * 64) * SROW + lmo;

    float acc[2][8][4];
    #pragma unroll
    for (int i = 0; i < 2; i++)
        #pragma unroll
        for (int j = 0; j < 8; j++)
            #pragma unroll
            for (int e = 0; e < 4; e++) acc[i][j][e] = 0.0f;

    // ---- prologue: issue loads for kc=0 (stage 0) and kc=1 (stage 1) ----
    #pragma unroll
    for (int s = 0; s < 8; s++)
        cpa16(sb + ld_so[s], gsrc[s >> 1] + ld_gi[s]);
    asm volatile("cp.async.commit_group;" ::: "memory");
    #pragma unroll
    for (int s = 0; s < 8; s++)
        cpa16(sb + STG + ld_so[s], gsrc[s >> 1] + ld_gi[s] + 4);
    asm volatile("cp.async.commit_group;" ::: "memory");

    #pragma unroll
    for (int kc = 0; kc < 4; kc++) {
        uint32_t stoff = (kc & 1) ? (uint32_t)STG : 0u;
        if (kc < 3) asm volatile("cp.async.wait_group 1;" ::: "memory");
        else        asm volatile("cp.async.wait_group 0;" ::: "memory");
        __syncthreads();
        #pragma unroll
        for (int ks = 0; ks < 2; ks++) {
            uint32_t ko = stoff + (uint32_t)(ks * 32);
            uint32_t ah[2][4], am[2][4];
            ldsm4(ah[0], aHi  + ko);
            ldsm4(ah[1], aHi  + ko + 16 * SROW);
            ldsm4(am[0], aMid + ko);
            ldsm4(am[1], aMid + ko + 16 * SROW);
            #pragma unroll
            for (int jp = 0; jp < 4; jp++) {
                uint32_t bh[4], bm[4];
                ldsm4(bh, bHi  + ko + (uint32_t)(jp * 16) * SROW);
                ldsm4(bm, bMid + ko + (uint32_t)(jp * 16) * SROW);
                #pragma unroll
                for (int i = 0; i < 2; i++) {
                    mma_bf16(acc[i][2 * jp],     ah[i], bh[0], bh[2]);
                    mma_bf16(acc[i][2 * jp],     am[i], bh[0], bh[2]);
                    mma_bf16(acc[i][2 * jp],     ah[i], bm[0], bm[2]);
                    mma_bf16(acc[i][2 * jp + 1], ah[i], bh[1], bh[3]);
                    mma_bf16(acc[i][2 * jp + 1], am[i], bh[1], bh[3]);
                    mma_bf16(acc[i][2 * jp + 1], ah[i], bm[1], bm[3]);
                }
            }
        }
        if (kc < 2) {
            __syncthreads();
            #pragma unroll
            for (int s = 0; s < 8; s++)
                cpa16(sb + stoff + ld_so[s], gsrc[s >> 1] + ld_gi[s] + (kc + 2) * 4);
            asm volatile("cp.async.commit_group;" ::: "memory");
        }
    }

    bool diag = (bi == bj);
    #pragma unroll
    for (int i = 0; i < 2; i++)
        #pragma unroll
        for (int j = 0; j < 8; j++)
            #pragma unroll
            for (int e = 0; e < 4; e++) {
                float x = an_exp(acc[i][j][e]);
                if (diag) {
                    int rl = wm * 32 + i * 16 + g + ((e >> 1) << 3);
                    int cl = wn * 64 + j * 8 + 2 * t + (e & 1);
                    if (rl == cl) x = 0.0f;
                }
                acc[i][j][e] = x;
            }
    // row sums
    #pragma unroll
    for (int i = 0; i < 2; i++)
        #pragma unroll
        for (int h = 0; h < 2; h++) {
            float v = 0.0f;
            #pragma unroll
            for (int j = 0; j < 8; j++) v += acc[i][j][2 * h] + acc[i][j][2 * h + 1];
            v += __shfl_xor_sync(0xffffffffu, v, 1);
            v += __shfl_xor_sync(0xffffffffu, v, 2);
            if (t == 0)
                atomicAdd(&g_sall[rowBase + wm * 32 + i * 16 + g + h * 8], v);
        }
    // col sums (only off-diagonal tiles)
    if (!diag) {
        #pragma unroll
        for (int j = 0; j < 8; j++)
            #pragma unroll
            for (int bb = 0; bb < 2; bb++) {
                float v = acc[0][j][bb] + acc[0][j][2 + bb] +
                          acc[1][j][bb] + acc[1][j][2 + bb];
                v += __shfl_xor_sync(0xffffffffu, v, 4);
                v += __shfl_xor_sync(0xffffffffu, v, 8);
                v += __shfl_xor_sync(0xffffffffu, v, 16);
                if (g == 0)
                    atomicAdd(&g_sall[colBase + wn * 64 + j * 8 + 2 * t + bb], v);
            }
    }
}

// ---------------- kernel 4: finalize loss + re-zero g_cnt ------------------
__global__ void k_final(const void* __restrict__ lab, float* __restrict__ out) {
    __shared__ float ssum[256];
    __shared__ int   scnt[256];
    int tid = threadIdx.x;
    float acc = 0.0f;
    int cnt = 0;
    for (int i = tid; i < N; i += 256) {
        int c = get_label(lab, i);
        int m = g_cnt[c];
        int np = m - 1, nn = N - m;
        if (np > 0 && nn > 0) {
            float sneg = g_sall[i] - g_samesum[i];
            sneg = fmaxf(sneg, 1e-30f);
            float x = g_lsep[i] + logf((float)nn) + logf(sneg) + logf((float)np);
            float sp = (x > 0.0f) ? (x + log1pf(__expf(-x))) : log1pf(__expf(x));
            acc += sp;
            cnt++;
        }
    }
    ssum[tid] = acc; scnt[tid] = cnt;
    __syncthreads();
    for (int s = 128; s > 0; s >>= 1) {
        if (tid < s) { ssum[tid] += ssum[tid + s]; scnt[tid] += scnt[tid + s]; }
        __syncthreads();
    }
    if (tid == 0) out[0] = ssum[0] / fmaxf((float)scnt[0], 1.0f);
    // re-zero g_cnt for the next deterministic replay (reads above are done)
    __syncthreads();
    for (int i = tid; i < NC; i += 256) g_cnt[i] = 0;
}

// ---------------- launch ---------------------------------------------------
extern "C" void kernel_launch(void* const* d_in, const int* in_sizes, int n_in,
                              void* d_out, int out_size) {
    const float* embeds = (const float*)d_in[0];
    const void*  labels = d_in[1];
    float* out = (float*)d_out;
    (void)in_sizes; (void)n_in; (void)out_size;

    cudaFuncSetAttribute(k_main_m, cudaFuncAttributeMaxDynamicSharedMemorySize, SMEM_SZ);

    k_norm<<<N / 8, 256>>>(embeds, labels);
    k_class<<<NC, 128>>>();
    k_main_m<<<2080, 256, SMEM_SZ>>>();
    k_final<<<1, 256>>>(labels, out);
}

// round 6
// speedup vs baseline: 1.9727x; 1.9727x over previous
#include <cuda_runtime.h>
#include <cuda_bf16.h>
#include <math.h>
#include <stdint.h>

#define N 8192
#define D 128
#define NC 512
#define MAXM 64

// ---------------- scratch (device globals; no allocation allowed) ----------
__device__ __align__(16) float g_enorm[N * D];
__device__ __align__(16) __nv_bfloat16 g_hi[N * D];
__device__ __align__(16) __nv_bfloat16 g_mid[N * D];
__device__ int   g_cnt[NC];
__device__ int   g_members[NC * MAXM];
__device__ float g_lsep[N];
__device__ float g_samesum[N];
__device__ float g_sall[N];
__device__ float g_part[32];
__device__ int   g_pcnt[32];
__device__ int   g_is64;

__device__ __forceinline__ float an_exp(float s) {
    float t = fmaxf(s + 0.4f, 0.0f);
    return __expf(80.0f * t * (s - 0.4f));
}

__device__ __forceinline__ int get_label(const void* lab, int i) {
    if (g_is64) return (int)((const long long*)lab)[i];
    return ((const int*)lab)[i];
}

__device__ __forceinline__ uint32_t smem_u32(const void* p) {
    uint32_t a;
    asm("{ .reg .u64 t; cvta.to.shared.u64 t, %1; cvt.u32.u64 %0, t; }" : "=r"(a) : "l"(p));
    return a;
}
__device__ __forceinline__ void cpa16(uint32_t dst, const void* src) {
    asm volatile("cp.async.cg.shared.global [%0], [%1], 16;" :: "r"(dst), "l"(src) : "memory");
}
__device__ __forceinline__ void ldsm4(uint32_t* r, uint32_t addr) {
    asm volatile("ldmatrix.sync.aligned.m8n8.x4.shared.b16 {%0,%1,%2,%3}, [%4];"
        : "=r"(r[0]), "=r"(r[1]), "=r"(r[2]), "=r"(r[3]) : "r"(addr));
}
__device__ __forceinline__ void mma_bf16(float* d, const uint32_t* a, uint32_t b0, uint32_t b1) {
    asm volatile(
        "mma.sync.aligned.m16n8k16.row.col.f32.bf16.bf16.f32 "
        "{%0,%1,%2,%3}, {%4,%5,%6,%7}, {%8,%9}, {%0,%1,%2,%3};\n"
        : "+f"(d[0]), "+f"(d[1]), "+f"(d[2]), "+f"(d[3])
        : "r"(a[0]), "r"(a[1]), "r"(a[2]), "r"(a[3]), "r"(b0), "r"(b1));
}

// ---------------- kernel 0: tiny pre (g_cnt zero + dtype flag) -------------
__global__ void k_pre(const void* lab) {
    int i = blockIdx.x * blockDim.x + threadIdx.x;
    if (i < NC) g_cnt[i] = 0;
    if (i == 0) {
        const int* w = (const int*)lab;
        int bad = 0;
        #pragma unroll
        for (int k = 1; k < 128; k += 2) bad |= w[k];
        g_is64 = (bad == 0);
    }
}

// ---------------- kernel 1: normalize + bf16 split + lists + zero sall -----
__global__ void k_norm(const float* __restrict__ in, const void* __restrict__ lab) {
    int gid = blockIdx.x * blockDim.x + threadIdx.x;
    if (gid < N) g_sall[gid] = 0.0f;
    int row  = blockIdx.x * 8 + (threadIdx.x >> 5);
    int lane = threadIdx.x & 31;
    float4 v = *(const float4*)(in + row * D + lane * 4);
    float ss = v.x * v.x + v.y * v.y + v.z * v.z + v.w * v.w;
    #pragma unroll
    for (int m = 16; m >= 1; m >>= 1) ss += __shfl_xor_sync(0xffffffffu, ss, m);
    float inv = 1.0f / fmaxf(sqrtf(ss), 1e-12f);
    float o[4] = {v.x * inv, v.y * inv, v.z * inv, v.w * inv};
    float4 of; of.x = o[0]; of.y = o[1]; of.z = o[2]; of.w = o[3];
    *(float4*)(g_enorm + row * D + lane * 4) = of;
    #pragma unroll
    for (int c = 0; c < 4; c++) {
        __nv_bfloat16 h = __float2bfloat16(o[c]);
        float r = o[c] - __bfloat162float(h);
        g_hi [row * D + lane * 4 + c] = h;
        g_mid[row * D + lane * 4 + c] = __float2bfloat16(r);
    }
    if (lane == 0) {
        int c = get_label(lab, row);
        int p = atomicAdd(&g_cnt[c], 1);
        if (p < MAXM) g_members[c * MAXM + p] = row;
    }
}

// ---------------- kernel 2: per-class positives, warp-per-anchor -----------
__global__ void k_class() {
    int c = blockIdx.x;
    __shared__ int   mlist[MAXM];
    __shared__ float se[MAXM * 129];
    int m = g_cnt[c];
    if (m > MAXM) m = MAXM;
    if (m == 0) return;
    int tid = threadIdx.x, lane = tid & 31, wid = tid >> 5;
    if (tid < m) mlist[tid] = g_members[c * MAXM + tid];
    __syncthreads();
    for (int p = tid; p < m * D; p += blockDim.x) {
        int r = p >> 7, k = p & 127;
        se[r * 129 + k] = g_enorm[mlist[r] * D + k];
    }
    __syncthreads();
    for (int a = wid; a < m; a += 4) {
        int b0 = lane, b1 = lane + 32;
        float s0 = 0.0f, s1 = 0.0f;
        const float* ra = se + a * 129;
        #pragma unroll 8
        for (int k = 0; k < D; k++) {
            float av = ra[k];
            s0 = fmaf(av, se[b0 * 129 + k], s0);
            s1 = fmaf(av, se[b1 * 129 + k], s1);
        }
        float ap0 = -1e30f, ap1 = -1e30f, an0 = 0.0f, an1 = 0.0f;
        bool v0 = (b0 < m && b0 != a), v1 = (b1 < m && b1 != a);
        if (v0) { ap0 = -80.0f * fmaxf(1.4f - s0, 0.0f) * (s0 - 0.6f); an0 = an_exp(s0); }
        if (v1) { ap1 = -80.0f * fmaxf(1.4f - s1, 0.0f) * (s1 - 0.6f); an1 = an_exp(s1); }
        float mx = fmaxf(ap0, ap1);
        #pragma unroll
        for (int k = 16; k >= 1; k >>= 1) mx = fmaxf(mx, __shfl_xor_sync(0xffffffffu, mx, k));
        float es = (v0 ? __expf(ap0 - mx) : 0.0f) + (v1 ? __expf(ap1 - mx) : 0.0f);
        float sa = an0 + an1;
        #pragma unroll
        for (int k = 16; k >= 1; k >>= 1) {
            es += __shfl_xor_sync(0xffffffffu, es, k);
            sa += __shfl_xor_sync(0xffffffffu, sa, k);
        }
        if (lane == 0) {
            g_lsep[mlist[a]]    = mx + logf(es);
            g_samesum[mlist[a]] = sa;
        }
    }
}

// ---------------- kernel 3: mma.sync + ldmatrix + cp.async (R4 proven) -----
#define SROW   144
#define SA_HI  0
#define SA_MID (128 * SROW)
#define SB_HI  (2 * 128 * SROW)
#define SB_MID (3 * 128 * SROW)
#define SMEM_SZ (4 * 128 * SROW)   // 73728 B

__global__ void __launch_bounds__(256, 2) k_main_m() {
    int b = blockIdx.x;
    int r = (int)((__fsqrt_rn(8.0f * (float)b + 1.0f) - 1.0f) * 0.5f);
    while ((r + 1) * (r + 2) / 2 <= b) r++;
    while (r * (r + 1) / 2 > b) r--;
    int bi = b - r * (r + 1) / 2;
    int bj = r;

    extern __shared__ char sm[];
    uint32_t sb = smem_u32(sm);
    int tid = threadIdx.x;
    int lane = tid & 31, wid = tid >> 5;
    int g = lane >> 2, t = lane & 3;
    int wm = wid & 3, wn = wid >> 2;
    int rowBase = bi * 128, colBase = bj * 128;

    uint32_t lmo = (uint32_t)((lane & 15) * SROW + (lane >> 4) * 16);
    uint32_t aBaseHi  = sb + SA_HI  + (uint32_t)(wm * 32) * SROW + lmo;
    uint32_t aBaseMid = sb + SA_MID + (uint32_t)(wm * 32) * SROW + lmo;
    uint32_t bBaseHi  = sb + SB_HI  + (uint32_t)(wn * 64) * SROW + lmo;
    uint32_t bBaseMid = sb + SB_MID + (uint32_t)(wn * 64) * SROW + lmo;

    float acc[2][8][4];
    #pragma unroll
    for (int i = 0; i < 2; i++)
        #pragma unroll
        for (int j = 0; j < 8; j++)
            #pragma unroll
            for (int e = 0; e < 4; e++) acc[i][j][e] = 0.0f;

    for (int kc = 0; kc < 2; kc++) {
        #pragma unroll
        for (int it = 0; it < 4; it++) {
            int idx = it * 256 + tid;
            int row = idx >> 3, k8 = idx & 7;
            uint32_t so = (uint32_t)(row * SROW + k8 * 16);
            size_t gA = (size_t)(rowBase + row) * 16 + kc * 8 + k8;
            size_t gB = (size_t)(colBase + row) * 16 + kc * 8 + k8;
            cpa16(sb + SA_HI  + so, (const uint4*)g_hi  + gA);
            cpa16(sb + SA_MID + so, (const uint4*)g_mid + gA);
            cpa16(sb + SB_HI  + so, (const uint4*)g_hi  + gB);
            cpa16(sb + SB_MID + so, (const uint4*)g_mid + gB);
        }
        asm volatile("cp.async.commit_group;" ::: "memory");
        asm volatile("cp.async.wait_group 0;" ::: "memory");
        __syncthreads();

        #pragma unroll
        for (int ks = 0; ks < 4; ks++) {
            uint32_t ko = (uint32_t)(ks * 32);
            uint32_t ah[2][4], am[2][4];
            ldsm4(ah[0], aBaseHi  + ko);
            ldsm4(ah[1], aBaseHi  + ko + 16 * SROW);
            ldsm4(am[0], aBaseMid + ko);
            ldsm4(am[1], aBaseMid + ko + 16 * SROW);
            #pragma unroll
            for (int jp = 0; jp < 4; jp++) {
                uint32_t bh[4], bm[4];
                ldsm4(bh, bBaseHi  + ko + (uint32_t)(jp * 16) * SROW);
                ldsm4(bm, bBaseMid + ko + (uint32_t)(jp * 16) * SROW);
                #pragma unroll
                for (int i = 0; i < 2; i++) {
                    mma_bf16(acc[i][2 * jp],     ah[i], bh[0], bh[2]);
                    mma_bf16(acc[i][2 * jp],     am[i], bh[0], bh[2]);
                    mma_bf16(acc[i][2 * jp],     ah[i], bm[0], bm[2]);
                    mma_bf16(acc[i][2 * jp + 1], ah[i], bh[1], bh[3]);
                    mma_bf16(acc[i][2 * jp + 1], am[i], bh[1], bh[3]);
                    mma_bf16(acc[i][2 * jp + 1], ah[i], bm[1], bm[3]);
                }
            }
        }
        __syncthreads();
    }

    bool diag = (bi == bj);
    #pragma unroll
    for (int i = 0; i < 2; i++)
        #pragma unroll
        for (int j = 0; j < 8; j++)
            #pragma unroll
            for (int e = 0; e < 4; e++) {
                float x = an_exp(acc[i][j][e]);
                if (diag) {
                    int rl = wm * 32 + i * 16 + g + ((e >> 1) << 3);
                    int cl = wn * 64 + j * 8 + 2 * t + (e & 1);
                    if (rl == cl) x = 0.0f;
                }
                acc[i][j][e] = x;
            }
    #pragma unroll
    for (int i = 0; i < 2; i++)
        #pragma unroll
        for (int h = 0; h < 2; h++) {
            float v = 0.0f;
            #pragma unroll
            for (int j = 0; j < 8; j++) v += acc[i][j][2 * h] + acc[i][j][2 * h + 1];
            v += __shfl_xor_sync(0xffffffffu, v, 1);
            v += __shfl_xor_sync(0xffffffffu, v, 2);
            if (t == 0)
                atomicAdd(&g_sall[rowBase + wm * 32 + i * 16 + g + h * 8], v);
        }
    if (!diag) {
        #pragma unroll
        for (int j = 0; j < 8; j++)
            #pragma unroll
            for (int bb = 0; bb < 2; bb++) {
                float v = acc[0][j][bb] + acc[0][j][2 + bb] +
                          acc[1][j][bb] + acc[1][j][2 + bb];
                v += __shfl_xor_sync(0xffffffffu, v, 4);
                v += __shfl_xor_sync(0xffffffffu, v, 8);
                v += __shfl_xor_sync(0xffffffffu, v, 16);
                if (g == 0)
                    atomicAdd(&g_sall[colBase + wn * 64 + j * 8 + 2 * t + bb], v);
            }
    }
}

// ---------------- kernel 4a: parallel finalize (one anchor per thread) -----
__global__ void k_finalp(const void* __restrict__ lab) {
    __shared__ float ssum[256];
    __shared__ int   scnt[256];
    int tid = threadIdx.x;
    int i = blockIdx.x * 256 + tid;
    int c = get_label(lab, i);
    int m = g_cnt[c];
    int np = m - 1, nn = N - m;
    float sp = 0.0f;
    int ok = 0;
    if (np > 0 && nn > 0) {
        float sneg = g_sall[i] - g_samesum[i];
        sneg = fmaxf(sneg, 1e-30f);
        float x = g_lsep[i] + logf((float)nn) + logf(sneg) + logf((float)np);
        sp = (x > 0.0f) ? (x + log1pf(__expf(-x))) : log1pf(__expf(x));
        ok = 1;
    }
    ssum[tid] = sp; scnt[tid] = ok;
    __syncthreads();
    #pragma unroll
    for (int s = 128; s > 0; s >>= 1) {
        if (tid < s) { ssum[tid] += ssum[tid + s]; scnt[tid] += scnt[tid + s]; }
        __syncthreads();
    }
    if (tid == 0) { g_part[blockIdx.x] = ssum[0]; g_pcnt[blockIdx.x] = scnt[0]; }
}

// ---------------- kernel 4b: deterministic 32-way reduce -------------------
__global__ void k_final2(float* __restrict__ out) {
    int lane = threadIdx.x;
    float v = g_part[lane];
    int   c = g_pcnt[lane];
    #pragma unroll
    for (int k = 16; k >= 1; k >>= 1) {
        v += __shfl_xor_sync(0xffffffffu, v, k);
        c += __shfl_xor_sync(0xffffffffu, c, k);
    }
    if (lane == 0) out[0] = v / fmaxf((float)c, 1.0f);
}

// ---------------- launch ---------------------------------------------------
extern "C" void kernel_launch(void* const* d_in, const int* in_sizes, int n_in,
                              void* d_out, int out_size) {
    const float* embeds = (const float*)d_in[0];
    const void*  labels = d_in[1];
    float* out = (float*)d_out;
    (void)in_sizes; (void)n_in; (void)out_size;

    cudaFuncSetAttribute(k_main_m, cudaFuncAttributeMaxDynamicSharedMemorySize, SMEM_SZ);

    k_pre<<<2, 256>>>(labels);
    k_norm<<<N / 8, 256>>>(embeds, labels);
    k_class<<<NC, 128>>>();
    k_main_m<<<2080, 256, SMEM_SZ>>>();
    k_finalp<<<32, 256>>>(labels);
    k_final2<<<1, 32>>>(out);
}